// round 6
// baseline (speedup 1.0000x reference)
#include <cuda_runtime.h>
#include <math.h>

// Problem constants
#define BATCH 4
#define LSEQ  4096
#define DMODEL 2048
#define DI    512
#define NL    3

typedef unsigned long long ull;

// Scratch: h transposed, layout [b][e][l]  (4*512*4096 floats = 32 MiB)
__device__ float g_h[(size_t)BATCH * DI * LSEQ];

// Packed fp32x2 FMA: d = a*b + d (elementwise on the pair). SASS: FFMA2.
#define FFMA2(dacc, av, bv) \
    asm("fma.rn.f32x2 %0, %1, %2, %0;" : "+l"(dacc) : "l"(av), "l"(bv))
#define DUP2(dst, s) \
    asm("mov.b64 %0, {%1, %1};" : "=l"(dst) : "f"(s))
#define UNPACK2(lo, hi, v) \
    asm("mov.b64 {%0, %1}, %2;" : "=f"(lo), "=f"(hi) : "l"(v))

// ---------------------------------------------------------------------------
// GEMM1: h[b][e][l] = sum_k x[b][l][k] * W_down[e][k]
// BM=BN=128, BK=16, 256 threads, 8x8 register tile (8x4 f32x2 pairs),
// 2-stage ping-pong, ONE barrier per K-tile, packed FFMA2 accumulation.
// A-operand dup'd on the fly (single rotating reg) to stay under 128 regs.
// ---------------------------------------------------------------------------
__global__ __launch_bounds__(256, 2) void gemm_down(const float* __restrict__ X,
                                                    const float* __restrict__ Wd) {
    __shared__ __align__(16) float As[2][16][132];
    __shared__ __align__(16) float Bs[2][16][132];
    const int tid = threadIdx.x;
    const int m0 = blockIdx.y * 128;
    const int n0 = blockIdx.x * 128;
    const int lr = tid >> 2;         // 0..63
    const int lc = (tid & 3) << 2;   // 0,4,8,12
    const int tx = tid & 15;
    const int ty = tid >> 4;

    const float* Ap = X  + (size_t)(m0 + lr) * DMODEL + lc;
    const float* Bp = Wd + (size_t)(n0 + lr) * DMODEL + lc;

    ull acc[8][4];
#pragma unroll
    for (int i = 0; i < 8; i++)
#pragma unroll
        for (int j = 0; j < 4; j++) acc[i][j] = 0ull;

    float4 ra[2], rb[2];

    // Prologue: load tile 0 and stage into buffer 0
#pragma unroll
    for (int h = 0; h < 2; h++) {
        ra[h] = *(const float4*)(Ap + (size_t)h * 64 * DMODEL);
        rb[h] = *(const float4*)(Bp + (size_t)h * 64 * DMODEL);
    }
    int buf = 0;
#pragma unroll
    for (int h = 0; h < 2; h++) {
        As[buf][lc + 0][lr + h * 64] = ra[h].x;
        As[buf][lc + 1][lr + h * 64] = ra[h].y;
        As[buf][lc + 2][lr + h * 64] = ra[h].z;
        As[buf][lc + 3][lr + h * 64] = ra[h].w;
        Bs[buf][lc + 0][lr + h * 64] = rb[h].x;
        Bs[buf][lc + 1][lr + h * 64] = rb[h].y;
        Bs[buf][lc + 2][lr + h * 64] = rb[h].z;
        Bs[buf][lc + 3][lr + h * 64] = rb[h].w;
    }
    __syncthreads();

    for (int k0 = 16; k0 <= DMODEL; k0 += 16) {
        // Issue next-tile global loads early (overlap with compute below)
        if (k0 < DMODEL) {
#pragma unroll
            for (int h = 0; h < 2; h++) {
                ra[h] = *(const float4*)(Ap + (size_t)h * 64 * DMODEL + k0);
                rb[h] = *(const float4*)(Bp + (size_t)h * 64 * DMODEL + k0);
            }
        }
        // Compute current tile with packed FFMA2
#pragma unroll
        for (int kk = 0; kk < 16; kk++) {
            float ar[8];
            ull bp[4];
            *(float4*)(ar)     = *(const float4*)(&As[buf][kk][ty * 8]);
            *(float4*)(ar + 4) = *(const float4*)(&As[buf][kk][ty * 8 + 4]);
            ulonglong2 b01 = *(const ulonglong2*)(&Bs[buf][kk][tx * 8]);
            ulonglong2 b23 = *(const ulonglong2*)(&Bs[buf][kk][tx * 8 + 4]);
            bp[0] = b01.x; bp[1] = b01.y; bp[2] = b23.x; bp[3] = b23.y;
#pragma unroll
            for (int i = 0; i < 8; i++) {
                ull ad;                       // single rotating dup register
                DUP2(ad, ar[i]);
#pragma unroll
                for (int j = 0; j < 4; j++) FFMA2(acc[i][j], ad, bp[j]);
            }
        }
        // Stage next tile into the other buffer; ONE barrier per tile.
        // Safe: buf^1 was last read before the previous barrier.
        if (k0 < DMODEL) {
            const int nb = buf ^ 1;
#pragma unroll
            for (int h = 0; h < 2; h++) {
                As[nb][lc + 0][lr + h * 64] = ra[h].x;
                As[nb][lc + 1][lr + h * 64] = ra[h].y;
                As[nb][lc + 2][lr + h * 64] = ra[h].z;
                As[nb][lc + 3][lr + h * 64] = ra[h].w;
                Bs[nb][lc + 0][lr + h * 64] = rb[h].x;
                Bs[nb][lc + 1][lr + h * 64] = rb[h].y;
                Bs[nb][lc + 2][lr + h * 64] = rb[h].z;
                Bs[nb][lc + 3][lr + h * 64] = rb[h].w;
            }
            __syncthreads();
            buf = nb;
        }
    }

    // Unpack accumulators: cc[i][j], i = row (l), j = col (e)
    float cc[8][8];
#pragma unroll
    for (int i = 0; i < 8; i++)
#pragma unroll
        for (int j = 0; j < 4; j++) UNPACK2(cc[i][2 * j], cc[i][2 * j + 1], acc[i][j]);

    // Epilogue: write transposed into g_h[b][e][l], vectorized over i (l-contiguous)
    const int b  = m0 >> 12;            // L = 4096
    const int l  = (m0 & (LSEQ - 1)) + ty * 8;
#pragma unroll
    for (int j = 0; j < 8; j++) {
        float* dst = g_h + ((size_t)b * DI + n0 + tx * 8 + j) * LSEQ + l;
        *(float4*)(dst)     = make_float4(cc[0][j], cc[1][j], cc[2][j], cc[3][j]);
        *(float4*)(dst + 4) = make_float4(cc[4][j], cc[5][j], cc[6][j], cc[7][j]);
    }
}

// ---------------------------------------------------------------------------
// Fused 3-layer causal EMA scan, in-place on g_h.
// One block per (b,e) row. 256 threads x 16 contiguous elements each.
// ---------------------------------------------------------------------------
__global__ __launch_bounds__(256) void scan_kernel(const float* __restrict__ log_a) {
    const int row  = blockIdx.x;            // b*DI + e
    const int e    = row & (DI - 1);
    float* base    = g_h + (size_t)row * LSEQ;
    const int tid  = threadIdx.x;
    const int lane = tid & 31;
    const int warp = tid >> 5;

    float v[16];
    const float4* src = (const float4*)(base + tid * 16);
#pragma unroll
    for (int q = 0; q < 4; q++) {
        float4 f = src[q];
        v[q * 4 + 0] = f.x; v[q * 4 + 1] = f.y;
        v[q * 4 + 2] = f.z; v[q * 4 + 3] = f.w;
    }

    __shared__ float sA[8], sB[8];

    for (int layer = 0; layer < NL; layer++) {
        const float la  = log_a[layer * DI + e];
        const float a   = 1.0f / (1.0f + expf(-la));
        const float oma = 1.0f - a;

        // Local scan with zero carry-in; v[i] becomes local y
        float y = 0.f;
#pragma unroll
        for (int i = 0; i < 16; i++) { y = a * y + oma * v[i]; v[i] = y; }

        // Segment transform: y_out = A*y_in + B, A = a^16, B = local last
        float a2 = a * a, a4 = a2 * a2, a8 = a4 * a4;
        float A  = a8 * a8;
        float Bv = v[15];

        // Inclusive warp scan of affine composition (time order = lane order)
#pragma unroll
        for (int d = 1; d < 32; d <<= 1) {
            float Ap = __shfl_up_sync(0xffffffffu, A, d);
            float Bp = __shfl_up_sync(0xffffffffu, Bv, d);
            if (lane >= d) { Bv = A * Bp + Bv; A = A * Ap; }
        }

        __syncthreads();                 // protect sA/sB reuse across layers
        if (lane == 31) { sA[warp] = A; sB[warp] = Bv; }
        __syncthreads();

        // Cross-warp exclusive prefix (carry into warp; y_init = 0)
        float cB = 0.f;
        for (int w = 0; w < warp; w++) cB = sA[w] * cB + sB[w];

        // Within-warp exclusive values
        float eA = __shfl_up_sync(0xffffffffu, A, 1);
        float eB = __shfl_up_sync(0xffffffffu, Bv, 1);
        if (lane == 0) { eA = 1.f; eB = 0.f; }

        const float carry = eA * cB + eB;   // y_{s-1} for this thread's segment

        // Apply carry: y_t = yloc_t + a^{t-s+1} * carry
        float ap = a;
#pragma unroll
        for (int i = 0; i < 16; i++) { v[i] += ap * carry; ap *= a; }
    }

    float4* dst = (float4*)(base + tid * 16);
#pragma unroll
    for (int q = 0; q < 4; q++)
        dst[q] = make_float4(v[q * 4 + 0], v[q * 4 + 1], v[q * 4 + 2], v[q * 4 + 3]);
}

// ---------------------------------------------------------------------------
// GEMM2: out[b][l][d] = sum_e W_up[d][e] * g_h[b][e][l]
// A tile (g_h) is natively [k][m]-coalesced; B (W_up) is K-contiguous.
// 2-stage ping-pong, ONE barrier per K-tile, packed FFMA2 accumulation.
// ---------------------------------------------------------------------------
__global__ __launch_bounds__(256, 2) void gemm_up(const float* __restrict__ Wu,
                                                  float* __restrict__ Out) {
    __shared__ __align__(16) float As[2][16][132];
    __shared__ __align__(16) float Bs[2][16][132];
    const int tid = threadIdx.x;
    const int m0 = blockIdx.y * 128;        // (b,l)
    const int n0 = blockIdx.x * 128;        // d
    const int b  = m0 >> 12;
    const int l0 = m0 & (LSEQ - 1);

    const int kr = tid >> 5;                // 0..7 (A loads)
    const int mc = (tid & 31) << 2;         // 0..124
    const int lr = tid >> 2;                // 0..63 (B loads)
    const int lc = (tid & 3) << 2;
    const int tx = tid & 15;
    const int ty = tid >> 4;

    const float* hbase = g_h + (size_t)b * DI * LSEQ;

    ull acc[8][4];
#pragma unroll
    for (int i = 0; i < 8; i++)
#pragma unroll
        for (int j = 0; j < 4; j++) acc[i][j] = 0ull;

    float4 ra[2], rb[2];

    // Prologue: load tile 0 and stage into buffer 0
#pragma unroll
    for (int h = 0; h < 2; h++) {
        ra[h] = *(const float4*)(hbase + (size_t)(kr + h * 8) * LSEQ + l0 + mc);
        rb[h] = *(const float4*)(Wu + (size_t)(n0 + lr + h * 64) * DI + lc);
    }
    int buf = 0;
#pragma unroll
    for (int h = 0; h < 2; h++) {
        *(float4*)(&As[buf][kr + h * 8][mc]) = ra[h];
        Bs[buf][lc + 0][lr + h * 64] = rb[h].x;
        Bs[buf][lc + 1][lr + h * 64] = rb[h].y;
        Bs[buf][lc + 2][lr + h * 64] = rb[h].z;
        Bs[buf][lc + 3][lr + h * 64] = rb[h].w;
    }
    __syncthreads();

    for (int k0 = 16; k0 <= DI; k0 += 16) {
        if (k0 < DI) {
#pragma unroll
            for (int h = 0; h < 2; h++) {
                ra[h] = *(const float4*)(hbase + (size_t)(k0 + kr + h * 8) * LSEQ + l0 + mc);
                rb[h] = *(const float4*)(Wu + (size_t)(n0 + lr + h * 64) * DI + k0 + lc);
            }
        }
#pragma unroll
        for (int kk = 0; kk < 16; kk++) {
            float ar[8];
            ull bp[4];
            *(float4*)(ar)     = *(const float4*)(&As[buf][kk][ty * 8]);
            *(float4*)(ar + 4) = *(const float4*)(&As[buf][kk][ty * 8 + 4]);
            ulonglong2 b01 = *(const ulonglong2*)(&Bs[buf][kk][tx * 8]);
            ulonglong2 b23 = *(const ulonglong2*)(&Bs[buf][kk][tx * 8 + 4]);
            bp[0] = b01.x; bp[1] = b01.y; bp[2] = b23.x; bp[3] = b23.y;
#pragma unroll
            for (int i = 0; i < 8; i++) {
                ull ad;                       // single rotating dup register
                DUP2(ad, ar[i]);
#pragma unroll
                for (int j = 0; j < 4; j++) FFMA2(acc[i][j], ad, bp[j]);
            }
        }
        if (k0 < DI) {
            const int nb = buf ^ 1;
#pragma unroll
            for (int h = 0; h < 2; h++) {
                *(float4*)(&As[nb][kr + h * 8][mc]) = ra[h];
                Bs[nb][lc + 0][lr + h * 64] = rb[h].x;
                Bs[nb][lc + 1][lr + h * 64] = rb[h].y;
                Bs[nb][lc + 2][lr + h * 64] = rb[h].z;
                Bs[nb][lc + 3][lr + h * 64] = rb[h].w;
            }
            __syncthreads();
            buf = nb;
        }
    }

    float cc[8][8];
#pragma unroll
    for (int i = 0; i < 8; i++)
#pragma unroll
        for (int j = 0; j < 4; j++) UNPACK2(cc[i][2 * j], cc[i][2 * j + 1], acc[i][j]);

#pragma unroll
    for (int i = 0; i < 8; i++) {
        int m = m0 + ty * 8 + i;
        float* dst = Out + (size_t)m * DMODEL + n0 + tx * 8;
        *(float4*)(dst)     = make_float4(cc[i][0], cc[i][1], cc[i][2], cc[i][3]);
        *(float4*)(dst + 4) = make_float4(cc[i][4], cc[i][5], cc[i][6], cc[i][7]);
    }
}

// ---------------------------------------------------------------------------
extern "C" void kernel_launch(void* const* d_in, const int* in_sizes, int n_in,
                              void* d_out, int out_size) {
    const float* x  = (const float*)d_in[0];   // [4,4096,2048]
    const float* Wd = (const float*)d_in[1];   // [512,2048]
    const float* Wu = (const float*)d_in[2];   // [2048,512]
    const float* la = (const float*)d_in[3];   // [3,512]
    float* out = (float*)d_out;                // [4,4096,2048]

    dim3 g1(DI / 128, (BATCH * LSEQ) / 128);         // 4 x 128
    gemm_down<<<g1, 256>>>(x, Wd);

    scan_kernel<<<BATCH * DI, 256>>>(la);            // 2048 blocks

    dim3 g2(DMODEL / 128, (BATCH * LSEQ) / 128);     // 16 x 128
    gemm_up<<<g2, 256>>>(Wu, out);
}

// round 11
// speedup vs baseline: 1.2237x; 1.2237x over previous
#include <cuda_runtime.h>
#include <math.h>

// Problem constants
#define BATCH 4
#define LSEQ  4096
#define DMODEL 2048
#define DI    512
#define NL    3

typedef unsigned long long ull;

// Scratch: h transposed, layout [b][e][l]  (4*512*4096 floats = 32 MiB)
__device__ float g_h[(size_t)BATCH * DI * LSEQ];

// Packed fp32x2 FMA: d = a*b + d (elementwise on the pair). SASS: FFMA2.
#define FFMA2(dacc, av, bv) \
    asm("fma.rn.f32x2 %0, %1, %2, %0;" : "+l"(dacc) : "l"(av), "l"(bv))
#define DUP2(dst, s) \
    asm("mov.b64 %0, {%1, %1};" : "=l"(dst) : "f"(s))
#define UNPACK2(lo, hi, v) \
    asm("mov.b64 {%0, %1}, %2;" : "=f"(lo), "=f"(hi) : "l"(v))

// ---------------------------------------------------------------------------
// GEMM1: h[b][e][l] = sum_k x[b][l][k] * W_down[e][k]
// BM=BN=128, BK=16, 256 threads, 8x8 register tile (8x4 f32x2 pairs),
// 2-stage ping-pong, ONE barrier per K-tile, packed FFMA2 accumulation.
// Fragments are SPLIT 4+4 (offset 64) -> conflict-free LDS (banks 0,4,..28).
// ---------------------------------------------------------------------------
__global__ __launch_bounds__(256, 2) void gemm_down(const float* __restrict__ X,
                                                    const float* __restrict__ Wd) {
    __shared__ __align__(16) float As[2][16][132];
    __shared__ __align__(16) float Bs[2][16][132];
    const int tid = threadIdx.x;
    const int m0 = blockIdx.y * 128;
    const int n0 = blockIdx.x * 128;
    const int lr = tid >> 2;         // 0..63
    const int lc = (tid & 3) << 2;   // 0,4,8,12
    const int tx = tid & 15;
    const int ty = tid >> 4;

    const float* Ap = X  + (size_t)(m0 + lr) * DMODEL + lc;
    const float* Bp = Wd + (size_t)(n0 + lr) * DMODEL + lc;

    ull acc[8][4];
#pragma unroll
    for (int i = 0; i < 8; i++)
#pragma unroll
        for (int j = 0; j < 4; j++) acc[i][j] = 0ull;

    float4 ra[2], rb[2];

    // Prologue: load tile 0 and stage into buffer 0
#pragma unroll
    for (int h = 0; h < 2; h++) {
        ra[h] = *(const float4*)(Ap + (size_t)h * 64 * DMODEL);
        rb[h] = *(const float4*)(Bp + (size_t)h * 64 * DMODEL);
    }
    int buf = 0;
#pragma unroll
    for (int h = 0; h < 2; h++) {
        As[buf][lc + 0][lr + h * 64] = ra[h].x;
        As[buf][lc + 1][lr + h * 64] = ra[h].y;
        As[buf][lc + 2][lr + h * 64] = ra[h].z;
        As[buf][lc + 3][lr + h * 64] = ra[h].w;
        Bs[buf][lc + 0][lr + h * 64] = rb[h].x;
        Bs[buf][lc + 1][lr + h * 64] = rb[h].y;
        Bs[buf][lc + 2][lr + h * 64] = rb[h].z;
        Bs[buf][lc + 3][lr + h * 64] = rb[h].w;
    }
    __syncthreads();

    for (int k0 = 16; k0 <= DMODEL; k0 += 16) {
        // Issue next-tile global loads early (overlap with compute below)
        if (k0 < DMODEL) {
#pragma unroll
            for (int h = 0; h < 2; h++) {
                ra[h] = *(const float4*)(Ap + (size_t)h * 64 * DMODEL + k0);
                rb[h] = *(const float4*)(Bp + (size_t)h * 64 * DMODEL + k0);
            }
        }
        // Compute current tile with packed FFMA2; split 4+4 fragments.
        // Rows: m = ty*4+0..3 and 64+ty*4+0..3. Cols: n = tx*4+0..3 and 64+tx*4+0..3.
#pragma unroll
        for (int kk = 0; kk < 16; kk++) {
            float ar[8];
            ull bp[4];
            *(float4*)(ar)     = *(const float4*)(&As[buf][kk][ty * 4]);
            *(float4*)(ar + 4) = *(const float4*)(&As[buf][kk][64 + ty * 4]);
            ulonglong2 b01 = *(const ulonglong2*)(&Bs[buf][kk][tx * 4]);
            ulonglong2 b23 = *(const ulonglong2*)(&Bs[buf][kk][64 + tx * 4]);
            bp[0] = b01.x; bp[1] = b01.y; bp[2] = b23.x; bp[3] = b23.y;
#pragma unroll
            for (int i = 0; i < 8; i++) {
                ull ad;                       // single rotating dup register
                DUP2(ad, ar[i]);
#pragma unroll
                for (int j = 0; j < 4; j++) FFMA2(acc[i][j], ad, bp[j]);
            }
        }
        // Stage next tile into the other buffer; ONE barrier per tile.
        if (k0 < DMODEL) {
            const int nb = buf ^ 1;
#pragma unroll
            for (int h = 0; h < 2; h++) {
                As[nb][lc + 0][lr + h * 64] = ra[h].x;
                As[nb][lc + 1][lr + h * 64] = ra[h].y;
                As[nb][lc + 2][lr + h * 64] = ra[h].z;
                As[nb][lc + 3][lr + h * 64] = ra[h].w;
                Bs[nb][lc + 0][lr + h * 64] = rb[h].x;
                Bs[nb][lc + 1][lr + h * 64] = rb[h].y;
                Bs[nb][lc + 2][lr + h * 64] = rb[h].z;
                Bs[nb][lc + 3][lr + h * 64] = rb[h].w;
            }
            __syncthreads();
            buf = nb;
        }
    }

    // Unpack: cc[i][jc], i = row index (0..3 -> ty*4+i, 4..7 -> 64+ty*4+i-4),
    //                    jc = col index (0..3 -> tx*4+jc, 4..7 -> 64+tx*4+jc-4)
    float cc[8][8];
#pragma unroll
    for (int i = 0; i < 8; i++)
#pragma unroll
        for (int j = 0; j < 4; j++) UNPACK2(cc[i][2 * j], cc[i][2 * j + 1], acc[i][j]);

    // Epilogue: write transposed into g_h[b][e][l], float4 along l
    const int b     = m0 >> 12;            // L = 4096
    const int lbase = (m0 & (LSEQ - 1));
#pragma unroll
    for (int h2 = 0; h2 < 2; h2++) {
#pragma unroll
        for (int jj = 0; jj < 4; jj++) {
            const int jc = h2 * 4 + jj;
            const int e  = n0 + h2 * 64 + tx * 4 + jj;
            float* dst = g_h + ((size_t)b * DI + e) * LSEQ + lbase;
            *(float4*)(dst + ty * 4)      = make_float4(cc[0][jc], cc[1][jc], cc[2][jc], cc[3][jc]);
            *(float4*)(dst + 64 + ty * 4) = make_float4(cc[4][jc], cc[5][jc], cc[6][jc], cc[7][jc]);
        }
    }
}

// ---------------------------------------------------------------------------
// Fused 3-layer causal EMA scan, in-place on g_h.
// One block per (b,e) row. 256 threads x 16 contiguous elements each.
// ---------------------------------------------------------------------------
__global__ __launch_bounds__(256) void scan_kernel(const float* __restrict__ log_a) {
    const int row  = blockIdx.x;            // b*DI + e
    const int e    = row & (DI - 1);
    float* base    = g_h + (size_t)row * LSEQ;
    const int tid  = threadIdx.x;
    const int lane = tid & 31;
    const int warp = tid >> 5;

    float v[16];
    const float4* src = (const float4*)(base + tid * 16);
#pragma unroll
    for (int q = 0; q < 4; q++) {
        float4 f = src[q];
        v[q * 4 + 0] = f.x; v[q * 4 + 1] = f.y;
        v[q * 4 + 2] = f.z; v[q * 4 + 3] = f.w;
    }

    __shared__ float sA[8], sB[8];

    for (int layer = 0; layer < NL; layer++) {
        const float la  = log_a[layer * DI + e];
        const float a   = 1.0f / (1.0f + expf(-la));
        const float oma = 1.0f - a;

        // Local scan with zero carry-in; v[i] becomes local y
        float y = 0.f;
#pragma unroll
        for (int i = 0; i < 16; i++) { y = a * y + oma * v[i]; v[i] = y; }

        // Segment transform: y_out = A*y_in + B, A = a^16, B = local last
        float a2 = a * a, a4 = a2 * a2, a8 = a4 * a4;
        float A  = a8 * a8;
        float Bv = v[15];

        // Inclusive warp scan of affine composition (time order = lane order)
#pragma unroll
        for (int d = 1; d < 32; d <<= 1) {
            float Ap = __shfl_up_sync(0xffffffffu, A, d);
            float Bp = __shfl_up_sync(0xffffffffu, Bv, d);
            if (lane >= d) { Bv = A * Bp + Bv; A = A * Ap; }
        }

        __syncthreads();                 // protect sA/sB reuse across layers
        if (lane == 31) { sA[warp] = A; sB[warp] = Bv; }
        __syncthreads();

        // Cross-warp exclusive prefix (carry into warp; y_init = 0)
        float cB = 0.f;
        for (int w = 0; w < warp; w++) cB = sA[w] * cB + sB[w];

        // Within-warp exclusive values
        float eA = __shfl_up_sync(0xffffffffu, A, 1);
        float eB = __shfl_up_sync(0xffffffffu, Bv, 1);
        if (lane == 0) { eA = 1.f; eB = 0.f; }

        const float carry = eA * cB + eB;   // y_{s-1} for this thread's segment

        // Apply carry: y_t = yloc_t + a^{t-s+1} * carry
        float ap = a;
#pragma unroll
        for (int i = 0; i < 16; i++) { v[i] += ap * carry; ap *= a; }
    }

    float4* dst = (float4*)(base + tid * 16);
#pragma unroll
    for (int q = 0; q < 4; q++)
        dst[q] = make_float4(v[q * 4 + 0], v[q * 4 + 1], v[q * 4 + 2], v[q * 4 + 3]);
}

// ---------------------------------------------------------------------------
// GEMM2: out[b][l][d] = sum_e W_up[d][e] * g_h[b][e][l]
// A tile (g_h) is natively [k][m]-coalesced; B (W_up) is K-contiguous.
// 2-stage ping-pong, ONE barrier per K-tile, packed FFMA2, split fragments.
// ---------------------------------------------------------------------------
__global__ __launch_bounds__(256, 2) void gemm_up(const float* __restrict__ Wu,
                                                  float* __restrict__ Out) {
    __shared__ __align__(16) float As[2][16][132];
    __shared__ __align__(16) float Bs[2][16][132];
    const int tid = threadIdx.x;
    const int m0 = blockIdx.y * 128;        // (b,l)
    const int n0 = blockIdx.x * 128;        // d
    const int b  = m0 >> 12;
    const int l0 = m0 & (LSEQ - 1);

    const int kr = tid >> 5;                // 0..7 (A loads)
    const int mc = (tid & 31) << 2;         // 0..124
    const int lr = tid >> 2;                // 0..63 (B loads)
    const int lc = (tid & 3) << 2;
    const int tx = tid & 15;
    const int ty = tid >> 4;

    const float* hbase = g_h + (size_t)b * DI * LSEQ;

    ull acc[8][4];
#pragma unroll
    for (int i = 0; i < 8; i++)
#pragma unroll
        for (int j = 0; j < 4; j++) acc[i][j] = 0ull;

    float4 ra[2], rb[2];

    // Prologue: load tile 0 and stage into buffer 0
#pragma unroll
    for (int h = 0; h < 2; h++) {
        ra[h] = *(const float4*)(hbase + (size_t)(kr + h * 8) * LSEQ + l0 + mc);
        rb[h] = *(const float4*)(Wu + (size_t)(n0 + lr + h * 64) * DI + lc);
    }
    int buf = 0;
#pragma unroll
    for (int h = 0; h < 2; h++) {
        *(float4*)(&As[buf][kr + h * 8][mc]) = ra[h];
        Bs[buf][lc + 0][lr + h * 64] = rb[h].x;
        Bs[buf][lc + 1][lr + h * 64] = rb[h].y;
        Bs[buf][lc + 2][lr + h * 64] = rb[h].z;
        Bs[buf][lc + 3][lr + h * 64] = rb[h].w;
    }
    __syncthreads();

    for (int k0 = 16; k0 <= DI; k0 += 16) {
        if (k0 < DI) {
#pragma unroll
            for (int h = 0; h < 2; h++) {
                ra[h] = *(const float4*)(hbase + (size_t)(k0 + kr + h * 8) * LSEQ + l0 + mc);
                rb[h] = *(const float4*)(Wu + (size_t)(n0 + lr + h * 64) * DI + k0 + lc);
            }
        }
#pragma unroll
        for (int kk = 0; kk < 16; kk++) {
            float ar[8];
            ull bp[4];
            *(float4*)(ar)     = *(const float4*)(&As[buf][kk][ty * 4]);
            *(float4*)(ar + 4) = *(const float4*)(&As[buf][kk][64 + ty * 4]);
            ulonglong2 b01 = *(const ulonglong2*)(&Bs[buf][kk][tx * 4]);
            ulonglong2 b23 = *(const ulonglong2*)(&Bs[buf][kk][64 + tx * 4]);
            bp[0] = b01.x; bp[1] = b01.y; bp[2] = b23.x; bp[3] = b23.y;
#pragma unroll
            for (int i = 0; i < 8; i++) {
                ull ad;                       // single rotating dup register
                DUP2(ad, ar[i]);
#pragma unroll
                for (int j = 0; j < 4; j++) FFMA2(acc[i][j], ad, bp[j]);
            }
        }
        if (k0 < DI) {
            const int nb = buf ^ 1;
#pragma unroll
            for (int h = 0; h < 2; h++) {
                *(float4*)(&As[nb][kr + h * 8][mc]) = ra[h];
                Bs[nb][lc + 0][lr + h * 64] = rb[h].x;
                Bs[nb][lc + 1][lr + h * 64] = rb[h].y;
                Bs[nb][lc + 2][lr + h * 64] = rb[h].z;
                Bs[nb][lc + 3][lr + h * 64] = rb[h].w;
            }
            __syncthreads();
            buf = nb;
        }
    }

    float cc[8][8];
#pragma unroll
    for (int i = 0; i < 8; i++)
#pragma unroll
        for (int j = 0; j < 4; j++) UNPACK2(cc[i][2 * j], cc[i][2 * j + 1], acc[i][j]);

    // Epilogue: rows m = m0 + {ty*4+i | 64+ty*4+i}, cols split at tx*4 / 64+tx*4
#pragma unroll
    for (int i = 0; i < 8; i++) {
        const int m = m0 + ((i < 4) ? (ty * 4 + i) : (64 + ty * 4 + (i - 4)));
        float* dst = Out + (size_t)m * DMODEL + n0;
        *(float4*)(dst + tx * 4)      = make_float4(cc[i][0], cc[i][1], cc[i][2], cc[i][3]);
        *(float4*)(dst + 64 + tx * 4) = make_float4(cc[i][4], cc[i][5], cc[i][6], cc[i][7]);
    }
}

// ---------------------------------------------------------------------------
extern "C" void kernel_launch(void* const* d_in, const int* in_sizes, int n_in,
                              void* d_out, int out_size) {
    const float* x  = (const float*)d_in[0];   // [4,4096,2048]
    const float* Wd = (const float*)d_in[1];   // [512,2048]
    const float* Wu = (const float*)d_in[2];   // [2048,512]
    const float* la = (const float*)d_in[3];   // [3,512]
    float* out = (float*)d_out;                // [4,4096,2048]

    dim3 g1(DI / 128, (BATCH * LSEQ) / 128);         // 4 x 128
    gemm_down<<<g1, 256>>>(x, Wd);

    scan_kernel<<<BATCH * DI, 256>>>(la);            // 2048 blocks

    dim3 g2(DMODEL / 128, (BATCH * LSEQ) / 128);     // 16 x 128
    gemm_up<<<g2, 256>>>(Wu, out);
}